// round 3
// baseline (speedup 1.0000x reference)
#include <cuda_runtime.h>
#include <math.h>
#include <stdint.h>

// ---------------------------------------------------------------------------
// Problem constants
// ---------------------------------------------------------------------------
#define NTOK 32768
#define TOKD 1024
#define HIDD 1024
#define SEND 256
#define KC   512

// d_out float offsets (flattened reference tuple, fp32)
#define CENT_OFF 0              // centroids         [512,256]
#define SE_OFF   131072         // sense_embeddings  [65536,256]
#define WC_OFF   16908288       // word_class        [65536]
#define SCL_OFF  16973824       // sense_class       [65536]
#define OT_OFF   17039360       // order_t           [32768]
#define CT_OFF   17072128       // counts_t          [512]
#define OI_OFF   17072640       // order_i           [32768]
#define CI_OFF   17105408       // counts_i          [512]

// ---------------------------------------------------------------------------
// Scratch (device globals — the sanctioned no-alloc workaround)
// ---------------------------------------------------------------------------
__device__ float g_h1[(size_t)NTOK * HIDD];   // 128 MB
__device__ float g_h2[(size_t)NTOK * HIDD];   // 128 MB
__device__ float g_c2[KC];
__device__ float g_e2[2 * NTOK];
__device__ int   g_sc[2 * NTOK];
__device__ int   g_counts[2 * KC];
__device__ int   g_offsets[2 * KC];

// ---------------------------------------------------------------------------
// Fused SGEMM + tanh:  C[N,M] = tanh(A[N,K] @ B[K,M]), all row-major fp32.
// BM=BN=128, BK=16, 256 threads, 8x8 microtile per thread.
// All problem dims divide the tile sizes (32768/128, 1024/128, 256/128, K%16==0).
// ---------------------------------------------------------------------------
__global__ __launch_bounds__(256, 2)
void gemm_tanh(const float* __restrict__ A, const float* __restrict__ B,
               float* __restrict__ C, int Kdim, int Mcols)
{
    __shared__ float As[16][132];   // transposed A tile, padded (+4 keeps 16B align)
    __shared__ float Bs[16][128];

    const int tid = threadIdx.x;
    const int tx  = tid & 15;        // 0..15  -> column group
    const int ty  = tid >> 4;        // 0..15  -> row group
    const int blockRow = blockIdx.y << 7;
    const int blockCol = blockIdx.x << 7;

    float acc[8][8];
#pragma unroll
    for (int i = 0; i < 8; ++i)
#pragma unroll
        for (int j = 0; j < 8; ++j) acc[i][j] = 0.0f;

    const int ar  = tid >> 2;          // A tile row (first half), +64 second half
    const int ac4 = (tid & 3) << 2;    // A tile col (float4)
    const int br  = tid >> 5;          // B tile row (first half), +8 second half
    const int bc4 = (tid & 31) << 2;   // B tile col (float4)

    for (int kt = 0; kt < Kdim; kt += 16) {
#pragma unroll
        for (int l = 0; l < 2; ++l) {
            int r = ar + l * 64;
            float4 v = *reinterpret_cast<const float4*>(
                A + (size_t)(blockRow + r) * Kdim + kt + ac4);
            As[ac4 + 0][r] = v.x; As[ac4 + 1][r] = v.y;
            As[ac4 + 2][r] = v.z; As[ac4 + 3][r] = v.w;
        }
#pragma unroll
        for (int l = 0; l < 2; ++l) {
            int r = br + l * 8;
            *reinterpret_cast<float4*>(&Bs[r][bc4]) =
                *reinterpret_cast<const float4*>(
                    B + (size_t)(kt + r) * Mcols + blockCol + bc4);
        }
        __syncthreads();

#pragma unroll
        for (int k = 0; k < 16; ++k) {
            float a[8], b[8];
#pragma unroll
            for (int i = 0; i < 8; ++i) a[i] = As[k][(ty << 3) + i];
#pragma unroll
            for (int j = 0; j < 8; ++j) b[j] = Bs[k][(tx << 3) + j];
#pragma unroll
            for (int i = 0; i < 8; ++i)
#pragma unroll
                for (int j = 0; j < 8; ++j)
                    acc[i][j] = fmaf(a[i], b[j], acc[i][j]);
        }
        __syncthreads();
    }

#pragma unroll
    for (int i = 0; i < 8; ++i) {
        float* p = C + (size_t)(blockRow + (ty << 3) + i) * Mcols
                     + blockCol + (tx << 3);
        float4 o0, o1;
        o0.x = tanhf(acc[i][0]); o0.y = tanhf(acc[i][1]);
        o0.z = tanhf(acc[i][2]); o0.w = tanhf(acc[i][3]);
        o1.x = tanhf(acc[i][4]); o1.y = tanhf(acc[i][5]);
        o1.z = tanhf(acc[i][6]); o1.w = tanhf(acc[i][7]);
        *reinterpret_cast<float4*>(p)     = o0;
        *reinterpret_cast<float4*>(p + 4) = o1;
    }
}

// ---------------------------------------------------------------------------
// centroids = tanh(raw) -> d_out
// ---------------------------------------------------------------------------
__global__ void centroid_tanh(const float* __restrict__ raw, float* __restrict__ out)
{
    int i = blockIdx.x * blockDim.x + threadIdx.x;   // 0..131071
    out[CENT_OFF + i] = tanhf(raw[i]);
}

// c2[k] = sum_d cent[k][d]^2 — one warp per centroid row
__global__ void c2_kernel(const float* __restrict__ cent)
{
    int w    = (blockIdx.x * blockDim.x + threadIdx.x) >> 5;
    int lane = threadIdx.x & 31;
    if (w >= KC) return;
    const float* row = cent + (size_t)w * SEND;
    float s = 0.0f;
#pragma unroll
    for (int j = 0; j < 8; ++j) { float v = row[lane + j * 32]; s = fmaf(v, v, s); }
#pragma unroll
    for (int o = 16; o > 0; o >>= 1) s += __shfl_xor_sync(0xffffffffu, s, o);
    if (lane == 0) g_c2[w] = s;
}

// e2[i] = sum_d se[i][d]^2 — one warp per token row
__global__ void e2_kernel(const float* __restrict__ SE, int modal)
{
    int w    = (blockIdx.x * blockDim.x + threadIdx.x) >> 5;
    int lane = threadIdx.x & 31;
    const float* row = SE + (size_t)w * SEND;
    float s = 0.0f;
#pragma unroll
    for (int j = 0; j < 8; ++j) { float v = row[lane + j * 32]; s = fmaf(v, v, s); }
#pragma unroll
    for (int o = 16; o > 0; o >>= 1) s += __shfl_xor_sync(0xffffffffu, s, o);
    if (lane == 0) g_e2[modal * NTOK + w] = s;
}

// ---------------------------------------------------------------------------
// Assignment: for each token (128 per block), score against all 512 centroids
// in 4 tiles of 128, GEMM-style; keep running (min, first-index).
// score = (c2[k] + e2[i]) - 2*dot(c_k, se_i)  — same grouping as reference.
// ---------------------------------------------------------------------------
__global__ __launch_bounds__(256)
void assign_kernel(const float* __restrict__ SE, const float* __restrict__ CENT,
                   int modal)
{
    __shared__ float As[16][132];   // sense-dims x tokens (transposed)
    __shared__ float Bs[16][132];   // sense-dims x centroids (transposed)
    __shared__ float rv[128][16];
    __shared__ int   ri[128][16];

    const int tid = threadIdx.x;
    const int tx  = tid & 15, ty = tid >> 4;
    const int rowBase = blockIdx.x << 7;

    const int lr  = tid >> 2;          // 0..63 (+64 for second half)
    const int lc4 = (tid & 3) << 2;

    float e2r[8];
#pragma unroll
    for (int i = 0; i < 8; ++i)
        e2r[i] = g_e2[modal * NTOK + rowBase + (ty << 3) + i];

    float bestV[8]; int bestI[8];
#pragma unroll
    for (int i = 0; i < 8; ++i) { bestV[i] = 3.4e38f; bestI[i] = 0; }

    for (int ct = 0; ct < KC; ct += 128) {
        float acc[8][8];
#pragma unroll
        for (int i = 0; i < 8; ++i)
#pragma unroll
            for (int j = 0; j < 8; ++j) acc[i][j] = 0.0f;

        for (int kt = 0; kt < SEND; kt += 16) {
#pragma unroll
            for (int l = 0; l < 2; ++l) {
                int r = lr + l * 64;
                float4 va = *reinterpret_cast<const float4*>(
                    SE + (size_t)(rowBase + r) * SEND + kt + lc4);
                As[lc4 + 0][r] = va.x; As[lc4 + 1][r] = va.y;
                As[lc4 + 2][r] = va.z; As[lc4 + 3][r] = va.w;
                float4 vb = *reinterpret_cast<const float4*>(
                    CENT + (size_t)(ct + r) * SEND + kt + lc4);
                Bs[lc4 + 0][r] = vb.x; Bs[lc4 + 1][r] = vb.y;
                Bs[lc4 + 2][r] = vb.z; Bs[lc4 + 3][r] = vb.w;
            }
            __syncthreads();
#pragma unroll
            for (int k = 0; k < 16; ++k) {
                float a[8], b[8];
#pragma unroll
                for (int i = 0; i < 8; ++i) a[i] = As[k][(ty << 3) + i];
#pragma unroll
                for (int j = 0; j < 8; ++j) b[j] = Bs[k][(tx << 3) + j];
#pragma unroll
                for (int i = 0; i < 8; ++i)
#pragma unroll
                    for (int j = 0; j < 8; ++j)
                        acc[i][j] = fmaf(a[i], b[j], acc[i][j]);
            }
            __syncthreads();
        }

        float c2v[8];
#pragma unroll
        for (int j = 0; j < 8; ++j) c2v[j] = g_c2[ct + (tx << 3) + j];
#pragma unroll
        for (int i = 0; i < 8; ++i)
#pragma unroll
            for (int j = 0; j < 8; ++j) {
                int col = ct + (tx << 3) + j;
                float s = (c2v[j] + e2r[i]) - 2.0f * acc[i][j];
                if (s < bestV[i] || (s == bestV[i] && col < bestI[i])) {
                    bestV[i] = s; bestI[i] = col;
                }
            }
    }

#pragma unroll
    for (int i = 0; i < 8; ++i) {
        rv[(ty << 3) + i][tx] = bestV[i];
        ri[(ty << 3) + i][tx] = bestI[i];
    }
    __syncthreads();
    if (tid < 128) {
        float bv = rv[tid][0]; int bi = ri[tid][0];
#pragma unroll
        for (int t = 1; t < 16; ++t) {
            float v = rv[tid][t]; int ix = ri[tid][t];
            if (v < bv || (v == bv && ix < bi)) { bv = v; bi = ix; }
        }
        g_sc[modal * NTOK + rowBase + tid] = bi;
    }
}

// ---------------------------------------------------------------------------
// Counting sort (stable == jnp.argsort(..., stable=True))
// ---------------------------------------------------------------------------
__global__ void zero_counts()
{
    int i = blockIdx.x * blockDim.x + threadIdx.x;
    if (i < 2 * KC) g_counts[i] = 0;
}

__global__ void count_kernel(int modal)
{
    int i = blockIdx.x * blockDim.x + threadIdx.x;   // 0..NTOK-1
    atomicAdd(&g_counts[modal * KC + g_sc[modal * NTOK + i]], 1);
}

__global__ void scan_kernel(int modal)
{
    __shared__ int tmp[KC];
    int t = threadIdx.x;
    int v = g_counts[modal * KC + t];
    tmp[t] = v;
    __syncthreads();
    for (int off = 1; off < KC; off <<= 1) {
        int x = (t >= off) ? tmp[t - off] : 0;
        __syncthreads();
        tmp[t] += x;
        __syncthreads();
    }
    g_offsets[modal * KC + t] = tmp[t] - v;   // exclusive prefix
}

// One block per class k; ordered ballot compaction preserves index order.
__global__ void scatter_kernel(int modal, float* __restrict__ order)
{
    const int k = blockIdx.x;
    const int base0 = modal * NTOK;
    __shared__ int warpTot[8];
    int base = g_offsets[modal * KC + k];
    int lane = threadIdx.x & 31, wid = threadIdx.x >> 5;

    for (int start = 0; start < NTOK; start += 256) {
        int i = start + threadIdx.x;
        bool m = (g_sc[base0 + i] == k);
        unsigned b = __ballot_sync(0xffffffffu, m);
        if (lane == 0) warpTot[wid] = __popc(b);
        __syncthreads();
        int woff = 0, tot = 0;
#pragma unroll
        for (int w = 0; w < 8; ++w) { int c = warpTot[w]; tot += c; if (w < wid) woff += c; }
        if (m) order[base + woff + __popc(b & ((1u << lane) - 1u))] = (float)i;
        base += tot;
        __syncthreads();
    }
}

// ---------------------------------------------------------------------------
// word_class / sense_class / counts as fp32
// ---------------------------------------------------------------------------
__global__ void finalize_kernel(float* __restrict__ out)
{
    int i = blockIdx.x * blockDim.x + threadIdx.x;   // 0..65535
    out[WC_OFF + i]  = (i < NTOK) ? 0.0f : 1.0f;
    out[SCL_OFF + i] = (float)g_sc[i];
}

__global__ void counts_out_kernel(float* __restrict__ out)
{
    int i = blockIdx.x * blockDim.x + threadIdx.x;   // 0..1023
    if (i < 2 * KC) {
        int m = i >> 9, k = i & 511;
        out[(m ? CI_OFF : CT_OFF) + k] = (float)g_counts[i];
    }
}

// ---------------------------------------------------------------------------
// Launch
// ---------------------------------------------------------------------------
extern "C" void kernel_launch(void* const* d_in, const int* in_sizes, int n_in,
                              void* d_out, int out_size)
{
    const float* emb[2] = { (const float*)d_in[0], (const float*)d_in[1] };
    const float* W1[2]  = { (const float*)d_in[2], (const float*)d_in[5] };
    const float* W2[2]  = { (const float*)d_in[3], (const float*)d_in[6] };
    const float* W3[2]  = { (const float*)d_in[4], (const float*)d_in[7] };
    const float* craw   = (const float*)d_in[8];
    float* out = (float*)d_out;

    float *h1 = nullptr, *h2 = nullptr;
    cudaGetSymbolAddress((void**)&h1, g_h1);
    cudaGetSymbolAddress((void**)&h2, g_h2);

    centroid_tanh<<<(KC * SEND) / 256, 256>>>(craw, out);
    c2_kernel<<<(KC * 32) / 256, 256>>>(out + CENT_OFF);
    zero_counts<<<4, 256>>>();

    for (int m = 0; m < 2; ++m) {
        float* se = out + SE_OFF + (size_t)m * NTOK * SEND;

        gemm_tanh<<<dim3(HIDD / 128, NTOK / 128), 256>>>(emb[m], W1[m], h1, TOKD, HIDD);
        gemm_tanh<<<dim3(HIDD / 128, NTOK / 128), 256>>>(h1,     W2[m], h2, HIDD, HIDD);
        gemm_tanh<<<dim3(SEND / 128, NTOK / 128), 256>>>(h2,     W3[m], se, HIDD, SEND);

        e2_kernel<<<(NTOK * 32) / 256, 256>>>(se, m);
        assign_kernel<<<NTOK / 128, 256>>>(se, out + CENT_OFF, m);

        count_kernel<<<NTOK / 256, 256>>>(m);
        scan_kernel<<<1, KC>>>(m);
        scatter_kernel<<<KC, 256>>>(m, out + (m ? OI_OFF : OT_OFF));
    }

    finalize_kernel<<<(2 * NTOK) / 256, 256>>>(out);
    counts_out_kernel<<<4, 256>>>(out);
}

// round 6
// speedup vs baseline: 1.6847x; 1.6847x over previous
#include <cuda_runtime.h>
#include <cuda_fp16.h>
#include <math.h>
#include <stdint.h>

// ---------------------------------------------------------------------------
// Problem constants
// ---------------------------------------------------------------------------
#define NTOK 32768
#define TOKD 1024
#define HIDD 1024
#define SEND 256
#define KC   512

// d_out float offsets (flattened reference tuple, fp32)
#define CENT_OFF 0              // centroids         [512,256]
#define SE_OFF   131072         // sense_embeddings  [65536,256]
#define WC_OFF   16908288       // word_class        [65536]
#define SCL_OFF  16973824       // sense_class       [65536]
#define OT_OFF   17039360       // order_t           [32768]
#define CT_OFF   17072128       // counts_t          [512]
#define OI_OFF   17072640       // order_i           [32768]
#define CI_OFF   17105408       // counts_i          [512]

// ---------------------------------------------------------------------------
// Scratch (device globals — the sanctioned no-alloc workaround)
// ---------------------------------------------------------------------------
__device__ float g_h1[(size_t)NTOK * HIDD];   // 128 MB
__device__ float g_h2[(size_t)NTOK * HIDD];   // 128 MB
__device__ float g_wt[(size_t)HIDD * HIDD];   // 4 MB transposed weights
__device__ float g_c2[KC];
__device__ float g_e2[2 * NTOK];
__device__ int   g_sc[2 * NTOK];
__device__ int   g_counts[2 * KC];
__device__ int   g_offsets[2 * KC];

// ---------------------------------------------------------------------------
// fp16x3 split-GEMM via mma.sync (arch-portable PTX; legacy HMMA on sm_100)
//   C[rows, Mcols] = tanh( OS * (A*SA)[rows,K] @ ((Bt*SB)[Mcols,K])^T )
// Split: x*S = hi + lo (both fp16); terms Ah*Bh + Ah*Bl + Al*Bh, fp32 accum.
// Dropped Al*Bl ~ 2^-22 relative -> fp32-class accuracy.
// ---------------------------------------------------------------------------
#define PITCH     36                   // halves per smem row (32 data + 4 pad)
#define STG_HALFS (4 * 128 * PITCH)    // Ah | Al | Bh | Bl  = 18432 halves
#define A_LO_OFF  (128 * PITCH)        // 4608
#define B_HI_OFF  (2 * 128 * PITCH)    // 9216
#define B_LO_OFF  (3 * 128 * PITCH)    // 13824
#define GEMM_SMEM (2 * STG_HALFS * 2)  // 73728 bytes (2 stages)

#define MMA16816(d, a, b) \
    asm volatile( \
        "mma.sync.aligned.m16n8k16.row.col.f32.f16.f16.f32 " \
        "{%0,%1,%2,%3}, {%4,%5,%6,%7}, {%8,%9}, {%0,%1,%2,%3};" \
        : "+f"((d)[0]), "+f"((d)[1]), "+f"((d)[2]), "+f"((d)[3]) \
        : "r"((a)[0]), "r"((a)[1]), "r"((a)[2]), "r"((a)[3]), \
          "r"((b)[0]), "r"((b)[1]))

__device__ __forceinline__ void split_sts(half* hi_p, half* lo_p,
                                          float4 v, float S)
{
    float f0 = v.x * S, f1 = v.y * S, f2 = v.z * S, f3 = v.w * S;
    half  h0 = __float2half_rn(f0), h1 = __float2half_rn(f1);
    half  h2 = __float2half_rn(f2), h3 = __float2half_rn(f3);
    half  l0 = __float2half_rn(f0 - __half2float(h0));
    half  l1 = __float2half_rn(f1 - __half2float(h1));
    half  l2 = __float2half_rn(f2 - __half2float(h2));
    half  l3 = __float2half_rn(f3 - __half2float(h3));
    *reinterpret_cast<half2*>(hi_p)     = __halves2half2(h0, h1);
    *reinterpret_cast<half2*>(hi_p + 2) = __halves2half2(h2, h3);
    *reinterpret_cast<half2*>(lo_p)     = __halves2half2(l0, l1);
    *reinterpret_cast<half2*>(lo_p + 2) = __halves2half2(l2, l3);
}

__global__ __launch_bounds__(256)
void gemm_mma_tanh(const float* __restrict__ A, const float* __restrict__ Bt,
                   float* __restrict__ C, int Kdim, int Mcols,
                   float SA, float SB, float OS)
{
    extern __shared__ __align__(16) char smem[];
    half* stg = reinterpret_cast<half*>(smem);

    const int tid  = threadIdx.x;
    const int lane = tid & 31, wid = tid >> 5;
    const int warpRow = wid >> 2;          // 0..1  -> 64-row band
    const int warpCol = wid & 3;           // 0..3  -> 32-col band
    const int g   = lane >> 2, tig = lane & 3;
    const int blockRow = blockIdx.y << 7;
    const int blockCol = blockIdx.x << 7;

    float acc[4][4][4];
#pragma unroll
    for (int mt = 0; mt < 4; ++mt)
#pragma unroll
        for (int nt = 0; nt < 4; ++nt)
#pragma unroll
            for (int r = 0; r < 4; ++r) acc[mt][nt][r] = 0.0f;

    const int chunks = Kdim >> 5;
    float4 av[4], bv[4];

    auto LDG = [&](int kt) {
#pragma unroll
        for (int l = 0; l < 4; ++l) {
            int slot = tid + (l << 8);
            int r = slot >> 3, q = slot & 7;
            av[l] = *reinterpret_cast<const float4*>(
                A + (size_t)(blockRow + r) * Kdim + kt + (q << 2));
            bv[l] = *reinterpret_cast<const float4*>(
                Bt + (size_t)(blockCol + r) * Kdim + kt + (q << 2));
        }
    };
    auto STS = [&](int s) {
        half* st = stg + s * STG_HALFS;
#pragma unroll
        for (int l = 0; l < 4; ++l) {
            int slot = tid + (l << 8);
            int r = slot >> 3, q = slot & 7;
            int off = r * PITCH + (q << 2);
            split_sts(st + off,            st + A_LO_OFF + off, av[l], SA);
            split_sts(st + B_HI_OFF + off, st + B_LO_OFF + off, bv[l], SB);
        }
    };
    auto COMPUTE = [&](int s) {
        const half* st = stg + s * STG_HALFS;
        const half* Ah = st;
        const half* Al = st + A_LO_OFF;
        const half* Bh = st + B_HI_OFF;
        const half* Bl = st + B_LO_OFF;
#pragma unroll
        for (int ks = 0; ks < 2; ++ks) {
            const int c0 = (ks << 4) + (tig << 1);
            uint32_t ah[4][4], al[4][4], bh[4][2], bl[4][2];
#pragma unroll
            for (int mt = 0; mt < 4; ++mt) {
                int r0 = (warpRow << 6) + (mt << 4) + g;
                ah[mt][0] = *reinterpret_cast<const uint32_t*>(Ah + r0 * PITCH + c0);
                ah[mt][1] = *reinterpret_cast<const uint32_t*>(Ah + (r0 + 8) * PITCH + c0);
                ah[mt][2] = *reinterpret_cast<const uint32_t*>(Ah + r0 * PITCH + c0 + 8);
                ah[mt][3] = *reinterpret_cast<const uint32_t*>(Ah + (r0 + 8) * PITCH + c0 + 8);
                al[mt][0] = *reinterpret_cast<const uint32_t*>(Al + r0 * PITCH + c0);
                al[mt][1] = *reinterpret_cast<const uint32_t*>(Al + (r0 + 8) * PITCH + c0);
                al[mt][2] = *reinterpret_cast<const uint32_t*>(Al + r0 * PITCH + c0 + 8);
                al[mt][3] = *reinterpret_cast<const uint32_t*>(Al + (r0 + 8) * PITCH + c0 + 8);
            }
#pragma unroll
            for (int nt = 0; nt < 4; ++nt) {
                int n0 = (warpCol << 5) + (nt << 3) + g;
                bh[nt][0] = *reinterpret_cast<const uint32_t*>(Bh + n0 * PITCH + c0);
                bh[nt][1] = *reinterpret_cast<const uint32_t*>(Bh + n0 * PITCH + c0 + 8);
                bl[nt][0] = *reinterpret_cast<const uint32_t*>(Bl + n0 * PITCH + c0);
                bl[nt][1] = *reinterpret_cast<const uint32_t*>(Bl + n0 * PITCH + c0 + 8);
            }
#pragma unroll
            for (int mt = 0; mt < 4; ++mt)
#pragma unroll
                for (int nt = 0; nt < 4; ++nt) MMA16816(acc[mt][nt], ah[mt], bh[nt]);
#pragma unroll
            for (int mt = 0; mt < 4; ++mt)
#pragma unroll
                for (int nt = 0; nt < 4; ++nt) MMA16816(acc[mt][nt], ah[mt], bl[nt]);
#pragma unroll
            for (int mt = 0; mt < 4; ++mt)
#pragma unroll
                for (int nt = 0; nt < 4; ++nt) MMA16816(acc[mt][nt], al[mt], bh[nt]);
        }
    };

    LDG(0);
    STS(0);
    __syncthreads();

    for (int c = 0; c < chunks; ++c) {
        if (c + 1 < chunks) LDG((c + 1) << 5);
        COMPUTE(c & 1);
        if (c + 1 < chunks) STS((c + 1) & 1);
        __syncthreads();
    }

    // ---- epilogue: stage C in smem for coalesced tanh + float4 stores
    float* cst = reinterpret_cast<float*>(smem);   // [128][132]
#pragma unroll
    for (int mt = 0; mt < 4; ++mt)
#pragma unroll
        for (int nt = 0; nt < 4; ++nt) {
            int r0 = (warpRow << 6) + (mt << 4) + g;
            int cc = (warpCol << 5) + (nt << 3) + (tig << 1);
            *reinterpret_cast<float2*>(cst + r0 * 132 + cc) =
                make_float2(acc[mt][nt][0], acc[mt][nt][1]);
            *reinterpret_cast<float2*>(cst + (r0 + 8) * 132 + cc) =
                make_float2(acc[mt][nt][2], acc[mt][nt][3]);
        }
    __syncthreads();
    {
        const int row  = tid >> 1;
        const int colh = (tid & 1) << 6;
        const float* src = cst + row * 132 + colh;
        float* dst = C + (size_t)(blockRow + row) * Mcols + blockCol + colh;
#pragma unroll
        for (int j = 0; j < 16; ++j) {
            float4 v = *reinterpret_cast<const float4*>(src + (j << 2));
            float4 o;
            o.x = tanhf(v.x * OS); o.y = tanhf(v.y * OS);
            o.z = tanhf(v.z * OS); o.w = tanhf(v.w * OS);
            *reinterpret_cast<float4*>(dst + (j << 2)) = o;
        }
    }
}

// ---------------------------------------------------------------------------
// Weight transpose: W[K,N] -> Wt[N,K]
// ---------------------------------------------------------------------------
__global__ void transpose_kernel(const float* __restrict__ W,
                                 float* __restrict__ Wt, int K, int N)
{
    __shared__ float t[32][33];
    const int bx = blockIdx.x << 5;   // n base
    const int by = blockIdx.y << 5;   // k base
#pragma unroll
    for (int j = 0; j < 32; j += 8)
        t[threadIdx.y + j][threadIdx.x] =
            W[(size_t)(by + threadIdx.y + j) * N + bx + threadIdx.x];
    __syncthreads();
#pragma unroll
    for (int j = 0; j < 32; j += 8)
        Wt[(size_t)(bx + threadIdx.y + j) * K + by + threadIdx.x] =
            t[threadIdx.x][threadIdx.y + j];
}

// ---------------------------------------------------------------------------
// centroids = tanh(raw) -> d_out
// ---------------------------------------------------------------------------
__global__ void centroid_tanh(const float* __restrict__ raw, float* __restrict__ out)
{
    int i = blockIdx.x * blockDim.x + threadIdx.x;
    out[CENT_OFF + i] = tanhf(raw[i]);
}

__global__ void c2_kernel(const float* __restrict__ cent)
{
    int w    = (blockIdx.x * blockDim.x + threadIdx.x) >> 5;
    int lane = threadIdx.x & 31;
    if (w >= KC) return;
    const float* row = cent + (size_t)w * SEND;
    float s = 0.0f;
#pragma unroll
    for (int j = 0; j < 8; ++j) { float v = row[lane + j * 32]; s = fmaf(v, v, s); }
#pragma unroll
    for (int o = 16; o > 0; o >>= 1) s += __shfl_xor_sync(0xffffffffu, s, o);
    if (lane == 0) g_c2[w] = s;
}

__global__ void e2_kernel(const float* __restrict__ SE, int modal)
{
    int w    = (blockIdx.x * blockDim.x + threadIdx.x) >> 5;
    int lane = threadIdx.x & 31;
    const float* row = SE + (size_t)w * SEND;
    float s = 0.0f;
#pragma unroll
    for (int j = 0; j < 8; ++j) { float v = row[lane + j * 32]; s = fmaf(v, v, s); }
#pragma unroll
    for (int o = 16; o > 0; o >>= 1) s += __shfl_xor_sync(0xffffffffu, s, o);
    if (lane == 0) g_e2[modal * NTOK + w] = s;
}

// ---------------------------------------------------------------------------
// Assignment (exact fp32; unchanged from the passing round-3 kernel)
// ---------------------------------------------------------------------------
__global__ __launch_bounds__(256)
void assign_kernel(const float* __restrict__ SE, const float* __restrict__ CENT,
                   int modal)
{
    __shared__ float As[16][132];
    __shared__ float Bs[16][132];
    __shared__ float rv[128][16];
    __shared__ int   ri[128][16];

    const int tid = threadIdx.x;
    const int tx  = tid & 15, ty = tid >> 4;
    const int rowBase = blockIdx.x << 7;

    const int lr  = tid >> 2;
    const int lc4 = (tid & 3) << 2;

    float e2r[8];
#pragma unroll
    for (int i = 0; i < 8; ++i)
        e2r[i] = g_e2[modal * NTOK + rowBase + (ty << 3) + i];

    float bestV[8]; int bestI[8];
#pragma unroll
    for (int i = 0; i < 8; ++i) { bestV[i] = 3.4e38f; bestI[i] = 0; }

    for (int ct = 0; ct < KC; ct += 128) {
        float acc[8][8];
#pragma unroll
        for (int i = 0; i < 8; ++i)
#pragma unroll
            for (int j = 0; j < 8; ++j) acc[i][j] = 0.0f;

        for (int kt = 0; kt < SEND; kt += 16) {
#pragma unroll
            for (int l = 0; l < 2; ++l) {
                int r = lr + l * 64;
                float4 va = *reinterpret_cast<const float4*>(
                    SE + (size_t)(rowBase + r) * SEND + kt + lc4);
                As[lc4 + 0][r] = va.x; As[lc4 + 1][r] = va.y;
                As[lc4 + 2][r] = va.z; As[lc4 + 3][r] = va.w;
                float4 vb = *reinterpret_cast<const float4*>(
                    CENT + (size_t)(ct + r) * SEND + kt + lc4);
                Bs[lc4 + 0][r] = vb.x; Bs[lc4 + 1][r] = vb.y;
                Bs[lc4 + 2][r] = vb.z; Bs[lc4 + 3][r] = vb.w;
            }
            __syncthreads();
#pragma unroll
            for (int k = 0; k < 16; ++k) {
                float a[8], b[8];
#pragma unroll
                for (int i = 0; i < 8; ++i) a[i] = As[k][(ty << 3) + i];
#pragma unroll
                for (int j = 0; j < 8; ++j) b[j] = Bs[k][(tx << 3) + j];
#pragma unroll
                for (int i = 0; i < 8; ++i)
#pragma unroll
                    for (int j = 0; j < 8; ++j)
                        acc[i][j] = fmaf(a[i], b[j], acc[i][j]);
            }
            __syncthreads();
        }

        float c2v[8];
#pragma unroll
        for (int j = 0; j < 8; ++j) c2v[j] = g_c2[ct + (tx << 3) + j];
#pragma unroll
        for (int i = 0; i < 8; ++i)
#pragma unroll
            for (int j = 0; j < 8; ++j) {
                int col = ct + (tx << 3) + j;
                float s = (c2v[j] + e2r[i]) - 2.0f * acc[i][j];
                if (s < bestV[i] || (s == bestV[i] && col < bestI[i])) {
                    bestV[i] = s; bestI[i] = col;
                }
            }
    }

#pragma unroll
    for (int i = 0; i < 8; ++i) {
        rv[(ty << 3) + i][tx] = bestV[i];
        ri[(ty << 3) + i][tx] = bestI[i];
    }
    __syncthreads();
    if (tid < 128) {
        float bv = rv[tid][0]; int bi = ri[tid][0];
#pragma unroll
        for (int t = 1; t < 16; ++t) {
            float v = rv[tid][t]; int ix = ri[tid][t];
            if (v < bv || (v == bv && ix < bi)) { bv = v; bi = ix; }
        }
        g_sc[modal * NTOK + rowBase + tid] = bi;
    }
}

// ---------------------------------------------------------------------------
// Counting sort (stable == jnp.argsort(..., stable=True))
// ---------------------------------------------------------------------------
__global__ void zero_counts()
{
    int i = blockIdx.x * blockDim.x + threadIdx.x;
    if (i < 2 * KC) g_counts[i] = 0;
}

__global__ void count_kernel(int modal)
{
    int i = blockIdx.x * blockDim.x + threadIdx.x;
    atomicAdd(&g_counts[modal * KC + g_sc[modal * NTOK + i]], 1);
}

__global__ void scan_kernel(int modal)
{
    __shared__ int tmp[KC];
    int t = threadIdx.x;
    int v = g_counts[modal * KC + t];
    tmp[t] = v;
    __syncthreads();
    for (int off = 1; off < KC; off <<= 1) {
        int x = (t >= off) ? tmp[t - off] : 0;
        __syncthreads();
        tmp[t] += x;
        __syncthreads();
    }
    g_offsets[modal * KC + t] = tmp[t] - v;
}

__global__ void scatter_kernel(int modal, float* __restrict__ order)
{
    const int k = blockIdx.x;
    const int base0 = modal * NTOK;
    __shared__ int warpTot[8];
    int base = g_offsets[modal * KC + k];
    int lane = threadIdx.x & 31, wid = threadIdx.x >> 5;

    for (int start = 0; start < NTOK; start += 256) {
        int i = start + threadIdx.x;
        bool m = (g_sc[base0 + i] == k);
        unsigned b = __ballot_sync(0xffffffffu, m);
        if (lane == 0) warpTot[wid] = __popc(b);
        __syncthreads();
        int woff = 0, tot = 0;
#pragma unroll
        for (int w = 0; w < 8; ++w) { int c = warpTot[w]; tot += c; if (w < wid) woff += c; }
        if (m) order[base + woff + __popc(b & ((1u << lane) - 1u))] = (float)i;
        base += tot;
        __syncthreads();
    }
}

// ---------------------------------------------------------------------------
// word_class / sense_class / counts as fp32
// ---------------------------------------------------------------------------
__global__ void finalize_kernel(float* __restrict__ out)
{
    int i = blockIdx.x * blockDim.x + threadIdx.x;
    out[WC_OFF + i]  = (i < NTOK) ? 0.0f : 1.0f;
    out[SCL_OFF + i] = (float)g_sc[i];
}

__global__ void counts_out_kernel(float* __restrict__ out)
{
    int i = blockIdx.x * blockDim.x + threadIdx.x;
    if (i < 2 * KC) {
        int m = i >> 9, k = i & 511;
        out[(m ? CI_OFF : CT_OFF) + k] = (float)g_counts[i];
    }
}

// ---------------------------------------------------------------------------
// Launch
// ---------------------------------------------------------------------------
extern "C" void kernel_launch(void* const* d_in, const int* in_sizes, int n_in,
                              void* d_out, int out_size)
{
    const float* emb[2] = { (const float*)d_in[0], (const float*)d_in[1] };
    const float* W1[2]  = { (const float*)d_in[2], (const float*)d_in[5] };
    const float* W2[2]  = { (const float*)d_in[3], (const float*)d_in[6] };
    const float* W3[2]  = { (const float*)d_in[4], (const float*)d_in[7] };
    const float* craw   = (const float*)d_in[8];
    float* out = (float*)d_out;

    float *h1 = nullptr, *h2 = nullptr, *wt = nullptr;
    cudaGetSymbolAddress((void**)&h1, g_h1);
    cudaGetSymbolAddress((void**)&h2, g_h2);
    cudaGetSymbolAddress((void**)&wt, g_wt);

    cudaFuncSetAttribute(gemm_mma_tanh,
                         cudaFuncAttributeMaxDynamicSharedMemorySize, GEMM_SMEM);

    const float SA = 16.0f, SB = 64.0f, OS = 1.0f / (16.0f * 64.0f);

    centroid_tanh<<<(KC * SEND) / 256, 256>>>(craw, out);
    c2_kernel<<<(KC * 32) / 256, 256>>>(out + CENT_OFF);
    zero_counts<<<4, 256>>>();

    for (int m = 0; m < 2; ++m) {
        float* se = out + SE_OFF + (size_t)m * NTOK * SEND;

        transpose_kernel<<<dim3(HIDD / 32, TOKD / 32), dim3(32, 8)>>>(W1[m], wt, TOKD, HIDD);
        gemm_mma_tanh<<<dim3(HIDD / 128, NTOK / 128), 256, GEMM_SMEM>>>(
            emb[m], wt, h1, TOKD, HIDD, SA, SB, OS);

        transpose_kernel<<<dim3(HIDD / 32, HIDD / 32), dim3(32, 8)>>>(W2[m], wt, HIDD, HIDD);
        gemm_mma_tanh<<<dim3(HIDD / 128, NTOK / 128), 256, GEMM_SMEM>>>(
            h1, wt, h2, HIDD, HIDD, SA, SB, OS);

        transpose_kernel<<<dim3(SEND / 32, HIDD / 32), dim3(32, 8)>>>(W3[m], wt, HIDD, SEND);
        gemm_mma_tanh<<<dim3(SEND / 128, NTOK / 128), 256, GEMM_SMEM>>>(
            h2, wt, se, HIDD, SEND, SA, SB, OS);

        e2_kernel<<<(NTOK * 32) / 256, 256>>>(se, m);
        assign_kernel<<<NTOK / 128, 256>>>(se, out + CENT_OFF, m);

        count_kernel<<<NTOK / 256, 256>>>(m);
        scan_kernel<<<1, KC>>>(m);
        scatter_kernel<<<KC, 256>>>(m, out + (m ? OI_OFF : OT_OFF));
    }

    finalize_kernel<<<(2 * NTOK) / 256, 256>>>(out);
    counts_out_kernel<<<4, 256>>>(out);
}

// round 7
// speedup vs baseline: 1.8899x; 1.1218x over previous
#include <cuda_runtime.h>
#include <cuda_fp16.h>
#include <math.h>
#include <stdint.h>

// ---------------------------------------------------------------------------
// Problem constants
// ---------------------------------------------------------------------------
#define NTOK 32768
#define TOKD 1024
#define HIDD 1024
#define SEND 256
#define KC   512

// d_out float offsets (flattened reference tuple, fp32)
#define CENT_OFF 0              // centroids         [512,256]
#define SE_OFF   131072         // sense_embeddings  [65536,256]
#define WC_OFF   16908288       // word_class        [65536]
#define SCL_OFF  16973824       // sense_class       [65536]
#define OT_OFF   17039360       // order_t           [32768]
#define CT_OFF   17072128       // counts_t          [512]
#define OI_OFF   17072640       // order_i           [32768]
#define CI_OFF   17105408       // counts_i          [512]

#define SCALE_A 16.0f
#define SCALE_B 64.0f
#define OSCALE  (1.0f / 1024.0f)

// ---------------------------------------------------------------------------
// Scratch (device globals — the sanctioned no-alloc workaround)
// ---------------------------------------------------------------------------
__device__ half  g_xh1[(size_t)NTOK * HIDD];   // 64 MB  activation hi (ping)
__device__ half  g_xl1[(size_t)NTOK * HIDD];   // 64 MB  activation lo (ping)
__device__ half  g_xh2[(size_t)NTOK * HIDD];   // 64 MB  activation hi (pong)
__device__ half  g_xl2[(size_t)NTOK * HIDD];   // 64 MB  activation lo (pong)
__device__ half  g_wh[(size_t)HIDD * HIDD];    // 2 MB   weight hi (transposed)
__device__ half  g_wl[(size_t)HIDD * HIDD];    // 2 MB   weight lo (transposed)
__device__ float g_c2[KC];
__device__ float g_e2[2 * NTOK];
__device__ int   g_sc[2 * NTOK];
__device__ int   g_counts[2 * KC];
__device__ int   g_offsets[2 * KC];

// ---------------------------------------------------------------------------
// Portable PTX helpers (all sm_80-era, valid under compute_100)
// ---------------------------------------------------------------------------
__device__ __forceinline__ uint32_t smem_u32(const void* p) {
    uint32_t a;
    asm("{ .reg .u64 t; cvta.to.shared.u64 t, %1; cvt.u32.u64 %0, t; }"
        : "=r"(a) : "l"(p));
    return a;
}

#define MMA16816(d, a, b) \
    asm volatile( \
        "mma.sync.aligned.m16n8k16.row.col.f32.f16.f16.f32 " \
        "{%0,%1,%2,%3}, {%4,%5,%6,%7}, {%8,%9}, {%0,%1,%2,%3};" \
        : "+f"((d)[0]), "+f"((d)[1]), "+f"((d)[2]), "+f"((d)[3]) \
        : "r"((a)[0]), "r"((a)[1]), "r"((a)[2]), "r"((a)[3]), \
          "r"((b)[0]), "r"((b)[1]))

#define LDMX4(r0, r1, r2, r3, addr) \
    asm volatile("ldmatrix.sync.aligned.m8n8.x4.shared.b16 {%0,%1,%2,%3}, [%4];" \
        : "=r"(r0), "=r"(r1), "=r"(r2), "=r"(r3) : "r"(addr))

#define CPA16(dst, src) \
    asm volatile("cp.async.ca.shared.global [%0], [%1], 16;" \
        :: "r"(dst), "l"(src))
#define CPA_COMMIT() asm volatile("cp.async.commit_group;")
#define CPA_WAIT1()  asm volatile("cp.async.wait_group 1;")
#define CPA_WAIT0()  asm volatile("cp.async.wait_group 0;")

__device__ __forceinline__ void split2(float f, half& h, half& l) {
    h = __float2half_rn(f);
    l = __float2half_rn(f - __half2float(h));
}

// ---------------------------------------------------------------------------
// fp16x3 split-GEMM, pre-split operands.
//   acc = Ah*Bh + Ah*Bl + Al*Bh  (fp32 accum);  out = tanh(acc * OSCALE)
// A halves: [rows][Kdim] row-major; B halves: [Mcols][Kdim] row-major (N-major).
// Tile 128x128, BK=32, 2-stage cp.async pipeline, ldmatrix fragments.
// Smem tile layout: pitch 40 halves (80 B) -> (5r+b)%8 permutation =>
// conflict-free for both 16B fills and ldmatrix 8-row phases.
// OUT_SPLIT=1: epilogue writes tanh pre-split (hi,lo)*SCALE_A for next layer.
// OUT_SPLIT=0: epilogue writes fp32 tanh.
// ---------------------------------------------------------------------------
#define TILE_B    10240         // 128 rows * 80 B
#define STAGE_B   40960         // Ah | Al | Bh | Bl tiles
#define GEMM_SMEM 81920         // 2 stages

template<int OUT_SPLIT>
__global__ __launch_bounds__(256)
void gemm_split(const half* __restrict__ Ah, const half* __restrict__ Al,
                const half* __restrict__ Bh, const half* __restrict__ Bl,
                float* __restrict__ Cf,
                half* __restrict__ Coh, half* __restrict__ Col,
                int Kdim, int Mcols)
{
    extern __shared__ __align__(16) char smem[];
    const uint32_t sb0 = smem_u32(smem);

    const int tid  = threadIdx.x;
    const int lane = tid & 31, wid = tid >> 5;
    const int warpRow = wid >> 2;           // 0..1  -> 64-row band
    const int warpCol = wid & 3;            // 0..3  -> 32-col band
    const int g = lane >> 2, tig = lane & 3;
    const int blockRow = blockIdx.y << 7;
    const int blockCol = blockIdx.x << 7;

    float acc[4][4][4];
#pragma unroll
    for (int mt = 0; mt < 4; ++mt)
#pragma unroll
        for (int nt = 0; nt < 4; ++nt)
#pragma unroll
            for (int r = 0; r < 4; ++r) acc[mt][nt][r] = 0.0f;

    // cp.async fill: thread -> (row, two 16B blocks)
    const int fr = tid >> 1;               // 0..127
    const int fb = (tid & 1) << 1;         // 0 or 2
    const half* srcA = Ah + (size_t)(blockRow + fr) * Kdim + fb * 8;
    const half* srcAl = Al + (size_t)(blockRow + fr) * Kdim + fb * 8;
    const half* srcB = Bh + (size_t)(blockCol + fr) * Kdim + fb * 8;
    const half* srcBl = Bl + (size_t)(blockCol + fr) * Kdim + fb * 8;
    const uint32_t dstBase = sb0 + fr * 80 + fb * 16;

    // ldmatrix per-lane offset (bytes): rows via lanes 0-15, k+8 via lanes 16-31
    const uint32_t loff = (uint32_t)(((lane & 7) + ((lane >> 3) & 1) * 8) * 80
                                     + ((lane >> 4) & 1) * 16);

    const int chunks = Kdim >> 5;

    auto ISSUE = [&](int c) {
        const int s = c & 1;
        const int kh = c << 5;             // k offset in halves
        uint32_t d = dstBase + s * STAGE_B;
        CPA16(d,              srcA + kh);  CPA16(d + 16,              srcA + kh + 8);
        CPA16(d + TILE_B,     srcAl + kh); CPA16(d + TILE_B + 16,     srcAl + kh + 8);
        CPA16(d + 2 * TILE_B, srcB + kh);  CPA16(d + 2 * TILE_B + 16, srcB + kh + 8);
        CPA16(d + 3 * TILE_B, srcBl + kh); CPA16(d + 3 * TILE_B + 16, srcBl + kh + 8);
    };

    auto COMPUTE = [&](int s) {
        const uint32_t base  = sb0 + s * STAGE_B;
        const uint32_t aBase = base + (warpRow * 64) * 80 + loff;
        const uint32_t bBase = base + 2 * TILE_B + (warpCol * 32) * 80 + loff;
#pragma unroll
        for (int ks = 0; ks < 2; ++ks) {
            const uint32_t kof = ks << 5;  // 16 halves = 32 bytes
            uint32_t ah[4][4], al[4][4], bh[4][2], bl[4][2];
#pragma unroll
            for (int mt = 0; mt < 4; ++mt) {
                uint32_t ad = aBase + mt * (16 * 80) + kof;
                LDMX4(ah[mt][0], ah[mt][1], ah[mt][2], ah[mt][3], ad);
                LDMX4(al[mt][0], al[mt][1], al[mt][2], al[mt][3], ad + TILE_B);
            }
#pragma unroll
            for (int p = 0; p < 2; ++p) {
                uint32_t bd = bBase + p * (16 * 80) + kof;
                uint32_t r0, r1, r2, r3;
                LDMX4(r0, r1, r2, r3, bd);
                bh[2 * p][0] = r0; bh[2 * p + 1][0] = r1;
                bh[2 * p][1] = r2; bh[2 * p + 1][1] = r3;
                LDMX4(r0, r1, r2, r3, bd + TILE_B);
                bl[2 * p][0] = r0; bl[2 * p + 1][0] = r1;
                bl[2 * p][1] = r2; bl[2 * p + 1][1] = r3;
            }
#pragma unroll
            for (int mt = 0; mt < 4; ++mt)
#pragma unroll
                for (int nt = 0; nt < 4; ++nt) MMA16816(acc[mt][nt], ah[mt], bh[nt]);
#pragma unroll
            for (int mt = 0; mt < 4; ++mt)
#pragma unroll
                for (int nt = 0; nt < 4; ++nt) MMA16816(acc[mt][nt], ah[mt], bl[nt]);
#pragma unroll
            for (int mt = 0; mt < 4; ++mt)
#pragma unroll
                for (int nt = 0; nt < 4; ++nt) MMA16816(acc[mt][nt], al[mt], bh[nt]);
        }
    };

    ISSUE(0);
    CPA_COMMIT();
    for (int c = 0; c < chunks; ++c) {
        if (c + 1 < chunks) {
            ISSUE(c + 1);
            CPA_COMMIT();
            CPA_WAIT1();
        } else {
            CPA_WAIT0();
        }
        __syncthreads();
        COMPUTE(c & 1);
        __syncthreads();
    }

    // ---- epilogue: stage fp32 acc in smem, then coalesced transform+store
    float* cst = reinterpret_cast<float*>(smem);   // [128][132]
#pragma unroll
    for (int mt = 0; mt < 4; ++mt)
#pragma unroll
        for (int nt = 0; nt < 4; ++nt) {
            int r0 = (warpRow << 6) + (mt << 4) + g;
            int cc = (warpCol << 5) + (nt << 3) + (tig << 1);
            *reinterpret_cast<float2*>(cst + r0 * 132 + cc) =
                make_float2(acc[mt][nt][0], acc[mt][nt][1]);
            *reinterpret_cast<float2*>(cst + (r0 + 8) * 132 + cc) =
                make_float2(acc[mt][nt][2], acc[mt][nt][3]);
        }
    __syncthreads();
    {
        const int row  = tid >> 1;
        const int colh = (tid & 1) << 6;
        const float* src = cst + row * 132 + colh;
        const size_t gb = (size_t)(blockRow + row) * Mcols + blockCol + colh;
#pragma unroll
        for (int j = 0; j < 16; ++j) {
            float4 v = *reinterpret_cast<const float4*>(src + (j << 2));
            float t0 = tanhf(v.x * OSCALE), t1 = tanhf(v.y * OSCALE);
            float t2 = tanhf(v.z * OSCALE), t3 = tanhf(v.w * OSCALE);
            if (OUT_SPLIT) {
                half h0, h1, h2, h3, l0, l1, l2, l3;
                split2(t0 * SCALE_A, h0, l0); split2(t1 * SCALE_A, h1, l1);
                split2(t2 * SCALE_A, h2, l2); split2(t3 * SCALE_A, h3, l3);
                half2 ph0 = __halves2half2(h0, h1), ph1 = __halves2half2(h2, h3);
                half2 pl0 = __halves2half2(l0, l1), pl1 = __halves2half2(l2, l3);
                uint2 uh, ul;
                uh.x = reinterpret_cast<uint32_t&>(ph0);
                uh.y = reinterpret_cast<uint32_t&>(ph1);
                ul.x = reinterpret_cast<uint32_t&>(pl0);
                ul.y = reinterpret_cast<uint32_t&>(pl1);
                *reinterpret_cast<uint2*>(Coh + gb + (j << 2)) = uh;
                *reinterpret_cast<uint2*>(Col + gb + (j << 2)) = ul;
            } else {
                float4 o; o.x = t0; o.y = t1; o.z = t2; o.w = t3;
                *reinterpret_cast<float4*>(Cf + gb + (j << 2)) = o;
            }
        }
    }
}

// ---------------------------------------------------------------------------
// emb fp32 -> (hi, lo) halves, scaled
// ---------------------------------------------------------------------------
__global__ void split_src(const float* __restrict__ X,
                          half* __restrict__ Xh, half* __restrict__ Xl)
{
    int i = blockIdx.x * blockDim.x + threadIdx.x;   // float4 index
    float4 v = reinterpret_cast<const float4*>(X)[i];
    half h0, h1, h2, h3, l0, l1, l2, l3;
    split2(v.x * SCALE_A, h0, l0); split2(v.y * SCALE_A, h1, l1);
    split2(v.z * SCALE_A, h2, l2); split2(v.w * SCALE_A, h3, l3);
    half2 ph0 = __halves2half2(h0, h1), ph1 = __halves2half2(h2, h3);
    half2 pl0 = __halves2half2(l0, l1), pl1 = __halves2half2(l2, l3);
    uint2 uh, ul;
    uh.x = reinterpret_cast<uint32_t&>(ph0); uh.y = reinterpret_cast<uint32_t&>(ph1);
    ul.x = reinterpret_cast<uint32_t&>(pl0); ul.y = reinterpret_cast<uint32_t&>(pl1);
    reinterpret_cast<uint2*>(Xh)[i] = uh;
    reinterpret_cast<uint2*>(Xl)[i] = ul;
}

// ---------------------------------------------------------------------------
// Weight transpose + split: W[K,N] fp32 -> Th/Tl[N,K] halves, scaled
// ---------------------------------------------------------------------------
__global__ void transpose_split(const float* __restrict__ W,
                                half* __restrict__ Th, half* __restrict__ Tl,
                                int K, int N)
{
    __shared__ float t[32][33];
    const int bx = blockIdx.x << 5;   // n base
    const int by = blockIdx.y << 5;   // k base
#pragma unroll
    for (int j = 0; j < 32; j += 8)
        t[threadIdx.y + j][threadIdx.x] =
            W[(size_t)(by + threadIdx.y + j) * N + bx + threadIdx.x];
    __syncthreads();
#pragma unroll
    for (int j = 0; j < 32; j += 8) {
        float f = t[threadIdx.x][threadIdx.y + j] * SCALE_B;
        half h, l;
        split2(f, h, l);
        size_t o = (size_t)(bx + threadIdx.y + j) * K + by + threadIdx.x;
        Th[o] = h;
        Tl[o] = l;
    }
}

// ---------------------------------------------------------------------------
// centroids = tanh(raw) -> d_out ; row sumsq kernels
// ---------------------------------------------------------------------------
__global__ void centroid_tanh(const float* __restrict__ raw, float* __restrict__ out)
{
    int i = blockIdx.x * blockDim.x + threadIdx.x;
    out[CENT_OFF + i] = tanhf(raw[i]);
}

__global__ void c2_kernel(const float* __restrict__ cent)
{
    int w    = (blockIdx.x * blockDim.x + threadIdx.x) >> 5;
    int lane = threadIdx.x & 31;
    if (w >= KC) return;
    const float* row = cent + (size_t)w * SEND;
    float s = 0.0f;
#pragma unroll
    for (int j = 0; j < 8; ++j) { float v = row[lane + j * 32]; s = fmaf(v, v, s); }
#pragma unroll
    for (int o = 16; o > 0; o >>= 1) s += __shfl_xor_sync(0xffffffffu, s, o);
    if (lane == 0) g_c2[w] = s;
}

__global__ void e2_kernel(const float* __restrict__ SE, int modal)
{
    int w    = (blockIdx.x * blockDim.x + threadIdx.x) >> 5;
    int lane = threadIdx.x & 31;
    const float* row = SE + (size_t)w * SEND;
    float s = 0.0f;
#pragma unroll
    for (int j = 0; j < 8; ++j) { float v = row[lane + j * 32]; s = fmaf(v, v, s); }
#pragma unroll
    for (int o = 16; o > 0; o >>= 1) s += __shfl_xor_sync(0xffffffffu, s, o);
    if (lane == 0) g_e2[modal * NTOK + w] = s;
}

// ---------------------------------------------------------------------------
// Assignment (exact fp32; unchanged from the passing round-3 kernel)
// ---------------------------------------------------------------------------
__global__ __launch_bounds__(256)
void assign_kernel(const float* __restrict__ SE, const float* __restrict__ CENT,
                   int modal)
{
    __shared__ float As[16][132];
    __shared__ float Bs[16][132];
    __shared__ float rv[128][16];
    __shared__ int   ri[128][16];

    const int tid = threadIdx.x;
    const int tx  = tid & 15, ty = tid >> 4;
    const int rowBase = blockIdx.x << 7;

    const int lr  = tid >> 2;
    const int lc4 = (tid & 3) << 2;

    float e2r[8];
#pragma unroll
    for (int i = 0; i < 8; ++i)
        e2r[i] = g_e2[modal * NTOK + rowBase + (ty << 3) + i];

    float bestV[8]; int bestI[8];
#pragma unroll
    for (int i = 0; i < 8; ++i) { bestV[i] = 3.4e38f; bestI[i] = 0; }

    for (int ct = 0; ct < KC; ct += 128) {
        float acc[8][8];
#pragma unroll
        for (int i = 0; i < 8; ++i)
#pragma unroll
            for (int j = 0; j < 8; ++j) acc[i][j] = 0.0f;

        for (int kt = 0; kt < SEND; kt += 16) {
#pragma unroll
            for (int l = 0; l < 2; ++l) {
                int r = lr + l * 64;
                float4 va = *reinterpret_cast<const float4*>(
                    SE + (size_t)(rowBase + r) * SEND + kt + lc4);
                As[lc4 + 0][r] = va.x; As[lc4 + 1][r] = va.y;
                As[lc4 + 2][r] = va.z; As[lc4 + 3][r] = va.w;
                float4 vb = *reinterpret_cast<const float4*>(
                    CENT + (size_t)(ct + r) * SEND + kt + lc4);
                Bs[lc4 + 0][r] = vb.x; Bs[lc4 + 1][r] = vb.y;
                Bs[lc4 + 2][r] = vb.z; Bs[lc4 + 3][r] = vb.w;
            }
            __syncthreads();
#pragma unroll
            for (int k = 0; k < 16; ++k) {
                float a[8], b[8];
#pragma unroll
                for (int i = 0; i < 8; ++i) a[i] = As[k][(ty << 3) + i];
#pragma unroll
                for (int j = 0; j < 8; ++j) b[j] = Bs[k][(tx << 3) + j];
#pragma unroll
                for (int i = 0; i < 8; ++i)
#pragma unroll
                    for (int j = 0; j < 8; ++j)
                        acc[i][j] = fmaf(a[i], b[j], acc[i][j]);
            }
            __syncthreads();
        }

        float c2v[8];
#pragma unroll
        for (int j = 0; j < 8; ++j) c2v[j] = g_c2[ct + (tx << 3) + j];
#pragma unroll
        for (int i = 0; i < 8; ++i)
#pragma unroll
            for (int j = 0; j < 8; ++j) {
                int col = ct + (tx << 3) + j;
                float s = (c2v[j] + e2r[i]) - 2.0f * acc[i][j];
                if (s < bestV[i] || (s == bestV[i] && col < bestI[i])) {
                    bestV[i] = s; bestI[i] = col;
                }
            }
    }

#pragma unroll
    for (int i = 0; i < 8; ++i) {
        rv[(ty << 3) + i][tx] = bestV[i];
        ri[(ty << 3) + i][tx] = bestI[i];
    }
    __syncthreads();
    if (tid < 128) {
        float bv = rv[tid][0]; int bi = ri[tid][0];
#pragma unroll
        for (int t = 1; t < 16; ++t) {
            float v = rv[tid][t]; int ix = ri[tid][t];
            if (v < bv || (v == bv && ix < bi)) { bv = v; bi = ix; }
        }
        g_sc[modal * NTOK + rowBase + tid] = bi;
    }
}

// ---------------------------------------------------------------------------
// Counting sort (stable == jnp.argsort(..., stable=True))
// ---------------------------------------------------------------------------
__global__ void zero_counts()
{
    int i = blockIdx.x * blockDim.x + threadIdx.x;
    if (i < 2 * KC) g_counts[i] = 0;
}

__global__ void count_kernel(int modal)
{
    int i = blockIdx.x * blockDim.x + threadIdx.x;
    atomicAdd(&g_counts[modal * KC + g_sc[modal * NTOK + i]], 1);
}

__global__ void scan_kernel(int modal)
{
    __shared__ int tmp[KC];
    int t = threadIdx.x;
    int v = g_counts[modal * KC + t];
    tmp[t] = v;
    __syncthreads();
    for (int off = 1; off < KC; off <<= 1) {
        int x = (t >= off) ? tmp[t - off] : 0;
        __syncthreads();
        tmp[t] += x;
        __syncthreads();
    }
    g_offsets[modal * KC + t] = tmp[t] - v;
}

__global__ void scatter_kernel(int modal, float* __restrict__ order)
{
    const int k = blockIdx.x;
    const int base0 = modal * NTOK;
    __shared__ int warpTot[8];
    int base = g_offsets[modal * KC + k];
    int lane = threadIdx.x & 31, wid = threadIdx.x >> 5;

    for (int start = 0; start < NTOK; start += 256) {
        int i = start + threadIdx.x;
        bool m = (g_sc[base0 + i] == k);
        unsigned b = __ballot_sync(0xffffffffu, m);
        if (lane == 0) warpTot[wid] = __popc(b);
        __syncthreads();
        int woff = 0, tot = 0;
#pragma unroll
        for (int w = 0; w < 8; ++w) { int c = warpTot[w]; tot += c; if (w < wid) woff += c; }
        if (m) order[base + woff + __popc(b & ((1u << lane) - 1u))] = (float)i;
        base += tot;
        __syncthreads();
    }
}

// ---------------------------------------------------------------------------
// word_class / sense_class / counts as fp32
// ---------------------------------------------------------------------------
__global__ void finalize_kernel(float* __restrict__ out)
{
    int i = blockIdx.x * blockDim.x + threadIdx.x;
    out[WC_OFF + i]  = (i < NTOK) ? 0.0f : 1.0f;
    out[SCL_OFF + i] = (float)g_sc[i];
}

__global__ void counts_out_kernel(float* __restrict__ out)
{
    int i = blockIdx.x * blockDim.x + threadIdx.x;
    if (i < 2 * KC) {
        int m = i >> 9, k = i & 511;
        out[(m ? CI_OFF : CT_OFF) + k] = (float)g_counts[i];
    }
}

// ---------------------------------------------------------------------------
// Launch
// ---------------------------------------------------------------------------
extern "C" void kernel_launch(void* const* d_in, const int* in_sizes, int n_in,
                              void* d_out, int out_size)
{
    const float* emb[2] = { (const float*)d_in[0], (const float*)d_in[1] };
    const float* W1[2]  = { (const float*)d_in[2], (const float*)d_in[5] };
    const float* W2[2]  = { (const float*)d_in[3], (const float*)d_in[6] };
    const float* W3[2]  = { (const float*)d_in[4], (const float*)d_in[7] };
    const float* craw   = (const float*)d_in[8];
    float* out = (float*)d_out;

    half *xh1, *xl1, *xh2, *xl2, *wh, *wl;
    cudaGetSymbolAddress((void**)&xh1, g_xh1);
    cudaGetSymbolAddress((void**)&xl1, g_xl1);
    cudaGetSymbolAddress((void**)&xh2, g_xh2);
    cudaGetSymbolAddress((void**)&xl2, g_xl2);
    cudaGetSymbolAddress((void**)&wh, g_wh);
    cudaGetSymbolAddress((void**)&wl, g_wl);

    cudaFuncSetAttribute(gemm_split<0>,
                         cudaFuncAttributeMaxDynamicSharedMemorySize, GEMM_SMEM);
    cudaFuncSetAttribute(gemm_split<1>,
                         cudaFuncAttributeMaxDynamicSharedMemorySize, GEMM_SMEM);

    centroid_tanh<<<(KC * SEND) / 256, 256>>>(craw, out);
    c2_kernel<<<(KC * 32) / 256, 256>>>(out + CENT_OFF);
    zero_counts<<<4, 256>>>();

    for (int m = 0; m < 2; ++m) {
        float* se = out + SE_OFF + (size_t)m * NTOK * SEND;

        split_src<<<(NTOK * TOKD / 4) / 256, 256>>>(emb[m], xh1, xl1);

        transpose_split<<<dim3(HIDD / 32, TOKD / 32), dim3(32, 8)>>>(W1[m], wh, wl, TOKD, HIDD);
        gemm_split<1><<<dim3(HIDD / 128, NTOK / 128), 256, GEMM_SMEM>>>(
            xh1, xl1, wh, wl, nullptr, xh2, xl2, TOKD, HIDD);

        transpose_split<<<dim3(HIDD / 32, HIDD / 32), dim3(32, 8)>>>(W2[m], wh, wl, HIDD, HIDD);
        gemm_split<1><<<dim3(HIDD / 128, NTOK / 128), 256, GEMM_SMEM>>>(
            xh2, xl2, wh, wl, nullptr, xh1, xl1, HIDD, HIDD);

        transpose_split<<<dim3(SEND / 32, HIDD / 32), dim3(32, 8)>>>(W3[m], wh, wl, HIDD, SEND);
        gemm_split<0><<<dim3(SEND / 128, NTOK / 128), 256, GEMM_SMEM>>>(
            xh1, xl1, wh, wl, se, nullptr, nullptr, HIDD, SEND);

        e2_kernel<<<(NTOK * 32) / 256, 256>>>(se, m);
        assign_kernel<<<NTOK / 128, 256>>>(se, out + CENT_OFF, m);

        count_kernel<<<NTOK / 256, 256>>>(m);
        scan_kernel<<<1, KC>>>(m);
        scatter_kernel<<<KC, 256>>>(m, out + (m ? OI_OFF : OT_OFF));
    }

    finalize_kernel<<<(2 * NTOK) / 256, 256>>>(out);
    counts_out_kernel<<<4, 256>>>(out);
}